// round 2
// baseline (speedup 1.0000x reference)
#include <cuda_runtime.h>
#include <cstdint>

#define DEVINL __device__ __forceinline__

namespace {

constexpr int HDIM = 128;
constexpr long long BROWS = 131072;
constexpr long long BH = BROWS * (long long)HDIM;
constexpr int THREADS = 256;
constexpr int M_TILE = 128;
constexpr int GRID = (int)(BROWS / M_TILE);  // 1024

constexpr int A_PITCH = 260;  // words; 260 % 32 == 4 -> conflict-free A frags
constexpr int B_PITCH = 264;  // words; 264 % 32 == 8 -> conflict-free B frags

// smem word offsets
constexpr int SW_BIAS = 0;                       // 512 words
constexpr int SW_A = 512;                        // 128*260 = 33280 words
constexpr int SW_B0 = SW_A + 128 * A_PITCH;      // 33792
constexpr int SW_B1 = SW_B0 + 32 * B_PITCH;
constexpr int SMEM_WORDS = SW_B1 + 32 * B_PITCH;
constexpr int SMEM_BYTES = SMEM_WORDS * 4;       // 202752 B

DEVINL void cp16(uint32_t saddr, const void* gaddr) {
    asm volatile("cp.async.cg.shared.global [%0], [%1], 16;"
                 :: "r"(saddr), "l"(gaddr) : "memory");
}
DEVINL void cp_commit() { asm volatile("cp.async.commit_group;" ::: "memory"); }
DEVINL void cp_wait0() { asm volatile("cp.async.wait_group 0;" ::: "memory"); }

DEVINL float totf32(float x) {
    uint32_t r;
    asm("cvt.rna.tf32.f32 %0, %1;" : "=r"(r) : "f"(x));
    return __uint_as_float(r);
}

DEVINL void mma8(float* d, const uint32_t* a, uint32_t b0, uint32_t b1) {
    asm volatile(
        "mma.sync.aligned.m16n8k8.row.col.f32.tf32.tf32.f32 "
        "{%0,%1,%2,%3}, {%4,%5,%6,%7}, {%8,%9}, {%0,%1,%2,%3};"
        : "+f"(d[0]), "+f"(d[1]), "+f"(d[2]), "+f"(d[3])
        : "r"(a[0]), "r"(a[1]), "r"(a[2]), "r"(a[3]), "r"(b0), "r"(b1));
}

DEVINL float sigf(float x) {
    return __fdividef(1.0f, 1.0f + __expf(-x));
}
DEVINL float tanhfast(float x) {
    return __fdividef(2.0f, 1.0f + __expf(-2.0f * x)) - 1.0f;
}

// Prefetch one 32k x 256col weight chunk into B buffer via 16B cp.async.
// kc in 0..7: kc<4 -> Wx rows kc*32..; kc>=4 -> Wh rows (kc-4)*32..
// column c = g*64 + n_off, global n = half*64 + n_off.
DEVINL void prefetch_chunk(const float* const* w8, int kc, int half,
                           uint32_t smem_base_u32, int buf, int tid) {
    const int n0 = half * 64;
    const uint32_t bbase =
        smem_base_u32 + (uint32_t)((buf ? SW_B1 : SW_B0) * 4);
#pragma unroll
    for (int i = 0; i < 8; i++) {
        int p = tid + i * 256;      // f4 index 0..2047
        int ii = p & 15;            // 16B unit within 64-col segment
        int g = (p >> 4) & 3;       // gate
        int r = p >> 6;             // k-row within chunk, 0..31
        const float* src = w8[(kc < 4 ? 0 : 4) + g] +
                           (size_t)((kc & 3) * 32 + r) * HDIM + n0 + ii * 4;
        uint32_t dst = bbase + (uint32_t)((r * B_PITCH + g * 64 + ii * 4) * 4);
        cp16(dst, src);
    }
}

__global__ void __launch_bounds__(THREADS, 1)
lstm_kernel(const float* __restrict__ x, const float* __restrict__ hprev,
            const float* __restrict__ cprev,
            const float* __restrict__ wxi, const float* __restrict__ wxf,
            const float* __restrict__ wxg, const float* __restrict__ wxo,
            const float* __restrict__ whi, const float* __restrict__ whf,
            const float* __restrict__ whg, const float* __restrict__ who,
            const float* __restrict__ bi, const float* __restrict__ bf,
            const float* __restrict__ bg, const float* __restrict__ bo,
            float* __restrict__ outh, float* __restrict__ outc, int writeC) {
    extern __shared__ float sm[];
    const int tid = threadIdx.x;
    const int lane = tid & 31;
    const int warp = tid >> 5;
    const int wM = warp >> 2;  // 0..1
    const int wN = warp & 3;   // 0..3
    const long long row0 = (long long)blockIdx.x * M_TILE;

    // biases -> smem [i|f|g|o] each 128
    sm[SW_BIAS + tid] = (tid < 128) ? bi[tid] : bf[tid - 128];
    sm[SW_BIAS + 256 + tid] = (tid < 128) ? bg[tid] : bo[tid - 128];

    // Stage A = [x | h] (128 rows x 256 k), tf32-rounded, pitch A_PITCH.
#pragma unroll
    for (int i = 0; i < 16; i++) {
        int p = tid + i * 256;  // f4 index 0..4095
        int r = p >> 5;
        int c4 = p & 31;
        float4 v = *reinterpret_cast<const float4*>(x + (row0 + r) * HDIM + c4 * 4);
        float* d = sm + SW_A + r * A_PITCH + c4 * 4;
        d[0] = totf32(v.x); d[1] = totf32(v.y);
        d[2] = totf32(v.z); d[3] = totf32(v.w);
        float4 w = *reinterpret_cast<const float4*>(hprev + (row0 + r) * HDIM + c4 * 4);
        float* d2 = d + 128;
        d2[0] = totf32(w.x); d2[1] = totf32(w.y);
        d2[2] = totf32(w.z); d2[3] = totf32(w.w);
    }

    const uint32_t smem_u32 = (uint32_t)__cvta_generic_to_shared(sm);
    const float* w8[8] = {wxi, wxf, wxg, wxo, whi, whf, whg, who};

    prefetch_chunk(w8, 0, 0, smem_u32, 0, tid);
    cp_commit();

    float acc[4][8][4];

#pragma unroll 1
    for (int half = 0; half < 2; half++) {
#pragma unroll
        for (int mi = 0; mi < 4; mi++)
#pragma unroll
            for (int f = 0; f < 8; f++)
#pragma unroll
                for (int q = 0; q < 4; q++) acc[mi][f][q] = 0.0f;

#pragma unroll 1
        for (int kc = 0; kc < 8; kc++) {
            cp_wait0();
            __syncthreads();
            if (kc < 7) {
                prefetch_chunk(w8, kc + 1, half, smem_u32, (kc + 1) & 1, tid);
            } else if (half == 0) {
                prefetch_chunk(w8, 0, 1, smem_u32, 0, tid);
            }
            cp_commit();

            const float* Bb = sm + (kc & 1 ? SW_B1 : SW_B0);
#pragma unroll
            for (int s = 0; s < 4; s++) {
                const int k = kc * 32 + s * 8;
                uint32_t afr[4][4];
#pragma unroll
                for (int mi = 0; mi < 4; mi++) {
                    const float* ap = sm + SW_A +
                        (wM * 64 + mi * 16 + (lane >> 2)) * A_PITCH + k + (lane & 3);
                    afr[mi][0] = __float_as_uint(ap[0]);
                    afr[mi][1] = __float_as_uint(ap[8 * A_PITCH]);
                    afr[mi][2] = __float_as_uint(ap[4]);
                    afr[mi][3] = __float_as_uint(ap[8 * A_PITCH + 4]);
                }
#pragma unroll
                for (int f = 0; f < 8; f++) {
                    const int cb = (f >> 1) * 64 + wN * 16 + (f & 1) * 8 + (lane >> 2);
                    const float* bp = Bb + (s * 8 + (lane & 3)) * B_PITCH + cb;
                    uint32_t b0 = __float_as_uint(bp[0]);
                    uint32_t b1 = __float_as_uint(bp[4 * B_PITCH]);
#pragma unroll
                    for (int mi = 0; mi < 4; mi++) mma8(acc[mi][f], afr[mi], b0, b1);
                }
            }
        }

        // Epilogue for this half: cols n = half*64 + wN*16 + j*8 + 2*(lane&3) + {0,1}
        const float* bsm = sm + SW_BIAS;
#pragma unroll
        for (int mi = 0; mi < 4; mi++) {
#pragma unroll
            for (int rh = 0; rh < 2; rh++) {
                const long long m = row0 + wM * 64 + mi * 16 + (lane >> 2) + rh * 8;
#pragma unroll
                for (int j = 0; j < 2; j++) {
                    const int n = half * 64 + wN * 16 + j * 8 + 2 * (lane & 3);
                    float2 cp2 = *reinterpret_cast<const float2*>(cprev + m * HDIM + n);
                    float hv[2], cv[2];
#pragma unroll
                    for (int col = 0; col < 2; col++) {
                        float ai = acc[mi][0 + j][rh * 2 + col] + bsm[n + col];
                        float af = acc[mi][2 + j][rh * 2 + col] + bsm[128 + n + col];
                        float ag = acc[mi][4 + j][rh * 2 + col] + bsm[256 + n + col];
                        float ao = acc[mi][6 + j][rh * 2 + col] + bsm[384 + n + col];
                        float ig = sigf(ai);
                        float fg = sigf(af);
                        float og = sigf(ao);
                        float gg = tanhfast(ag);
                        float cpv = (col == 0) ? cp2.x : cp2.y;
                        float ct = fg * cpv + ig * gg;
                        cv[col] = ct;
                        hv[col] = og * tanhfast(ct);
                    }
                    *reinterpret_cast<float2*>(outh + m * HDIM + n) =
                        make_float2(hv[0], hv[1]);
                    if (writeC) {
                        *reinterpret_cast<float2*>(outc + m * HDIM + n) =
                            make_float2(cv[0], cv[1]);
                    }
                }
            }
        }
    }
}

}  // namespace

extern "C" void kernel_launch(void* const* d_in, const int* in_sizes, int n_in,
                              void* d_out, int out_size) {
    (void)in_sizes; (void)n_in;
    cudaFuncSetAttribute(lstm_kernel, cudaFuncAttributeMaxDynamicSharedMemorySize,
                         SMEM_BYTES);
    const float* x     = (const float*)d_in[0];
    const float* hprev = (const float*)d_in[1];
    const float* cprev = (const float*)d_in[2];
    const float* wxi   = (const float*)d_in[3];
    const float* wxf   = (const float*)d_in[4];
    const float* wxg   = (const float*)d_in[5];
    const float* wxo   = (const float*)d_in[6];
    const float* whi   = (const float*)d_in[7];
    const float* whf   = (const float*)d_in[8];
    const float* whg   = (const float*)d_in[9];
    const float* who   = (const float*)d_in[10];
    const float* bi    = (const float*)d_in[11];
    const float* bf    = (const float*)d_in[12];
    const float* bg    = (const float*)d_in[13];
    const float* bo    = (const float*)d_in[14];

    float* outh = (float*)d_out;
    const long long need2 = 2LL * BH;
    int writeC = ((long long)out_size >= need2) ? 1 : 0;
    float* outc = outh + BH;

    lstm_kernel<<<GRID, THREADS, SMEM_BYTES>>>(
        x, hprev, cprev, wxi, wxf, wxg, wxo, whi, whf, whg, who,
        bi, bf, bg, bo, outh, outc, writeC);
}